// round 6
// baseline (speedup 1.0000x reference)
#include <cuda_runtime.h>
#include <mma.h>
#include <math.h>

using namespace nvcuda;

// Problem constants
#define BATCH   4
#define HH      64
#define WW      64
#define CIN     128
#define FILTERS 128
#define HEADS   8
#define HSIZE   16
#define K0      7
#define K1      7
#define KD      49
#define NPIX    (BATCH*HH*WW)      // 16384
#define NQKV    384                 // q|k|v concat

typedef unsigned long long ull;

// packed f32x2 helpers (sm_100+)
#define FMA2(d, a, b)   asm("fma.rn.f32x2 %0, %1, %2, %0;" : "+l"(d) : "l"(a), "l"(b))
#define MUL2(d, a, b)   asm("mul.rn.f32x2 %0, %1, %2;"     : "=l"(d) : "l"(a), "l"(b))
#define ADD2(d, a, b)   asm("add.rn.f32x2 %0, %1, %2;"     : "=l"(d) : "l"(a), "l"(b))
#define PACK2(d, x, y)  asm("mov.b64 %0, {%1, %2};" : "=l"(d) : "f"(x), "f"(y))
#define UNPK2(lo, hi, s) asm("mov.b64 {%0, %1}, %2;" : "=f"(lo), "=f"(hi) : "l"(s))

__device__ float g_QKV[NPIX * NQKV];

// ---------------------------------------------------------------------------
// Kernel A: fused QKV projection, 3xTF32 WMMA (near-fp32 accuracy).
// C = X(16384x128) @ [Wq|Wk|Wv](128x384) + b
// BM=128 x BN=128 x BK=32, 256 threads (8 warps 4x2, warp tile 32x64).
// Dekker split done ONCE at smem store: x = hi + lo, both tf32-exact.
// D = Ahi*Bhi + Ahi*Blo + Alo*Bhi  (error ~2^-22, fp32-class).
// ---------------------------------------------------------------------------
#define GBM 128
#define GBN 128
#define GBK 32
#define ALD 36
#define BLD 132
#define CLD 132
#define A_ELEMS (GBM * ALD)          // 4608
#define B_ELEMS (GBK * BLD)          // 4224
#define GEMM_SMEM ((2 * A_ELEMS + 2 * B_ELEMS) * 4)   // 70656 B

__global__ __launch_bounds__(256)
void qkv_gemm_kernel(const float* __restrict__ X,
                     const float* __restrict__ Wq, const float* __restrict__ bq,
                     const float* __restrict__ Wk, const float* __restrict__ bk,
                     const float* __restrict__ Wv, const float* __restrict__ bv,
                     float* __restrict__ QKV)
{
    extern __shared__ float gsm[];
    float* Ahi = gsm;
    float* Alo = gsm + A_ELEMS;
    float* Bhi = gsm + 2 * A_ELEMS;
    float* Blo = gsm + 2 * A_ELEMS + B_ELEMS;
    float* Cst = gsm;                // epilogue staging (aliases tiles)

    const int bm = blockIdx.x * GBM;
    const int bn = blockIdx.y * GBN;   // 0 / 128 / 256 -> q / k / v exactly

    const float* W;  const float* bias;
    if (bn == 0)        { W = Wq; bias = bq; }
    else if (bn == 128) { W = Wk; bias = bk; }
    else                { W = Wv; bias = bv; }

    const int tid = threadIdx.x;
    const int wid = tid >> 5;
    const int warp_m = wid & 3;        // 4 row-warps x 32 rows
    const int warp_n = wid >> 2;       // 2 col-warps x 64 cols

    wmma::fragment<wmma::accumulator, 16, 16, 8, float> acc[2][4];
#pragma unroll
    for (int i = 0; i < 2; i++)
#pragma unroll
        for (int j = 0; j < 4; j++) wmma::fill_fragment(acc[i][j], 0.f);

    for (int kt = 0; kt < CIN; kt += GBK) {
        // ---- load + split A tile: 128 x 32 (1024 float4) ----
#pragma unroll
        for (int l = 0; l < 4; l++) {
            const int idx = tid + l * 256;
            const int r = idx >> 3, c4 = idx & 7;
            float4 v = *(const float4*)(X + (size_t)(bm + r) * CIN + kt + c4 * 4);
            float4 h, o;
            h.x = wmma::__float_to_tf32(v.x); o.x = wmma::__float_to_tf32(v.x - h.x);
            h.y = wmma::__float_to_tf32(v.y); o.y = wmma::__float_to_tf32(v.y - h.y);
            h.z = wmma::__float_to_tf32(v.z); o.z = wmma::__float_to_tf32(v.z - h.z);
            h.w = wmma::__float_to_tf32(v.w); o.w = wmma::__float_to_tf32(v.w - h.w);
            *(float4*)&Ahi[r * ALD + c4 * 4] = h;
            *(float4*)&Alo[r * ALD + c4 * 4] = o;
        }
        // ---- load + split B tile: 32 x 128 (1024 float4) ----
#pragma unroll
        for (int l = 0; l < 4; l++) {
            const int idx = tid + l * 256;
            const int r = idx >> 5, c4 = idx & 31;
            float4 v = *(const float4*)(W + (size_t)(kt + r) * FILTERS + c4 * 4);
            float4 h, o;
            h.x = wmma::__float_to_tf32(v.x); o.x = wmma::__float_to_tf32(v.x - h.x);
            h.y = wmma::__float_to_tf32(v.y); o.y = wmma::__float_to_tf32(v.y - h.y);
            h.z = wmma::__float_to_tf32(v.z); o.z = wmma::__float_to_tf32(v.z - h.z);
            h.w = wmma::__float_to_tf32(v.w); o.w = wmma::__float_to_tf32(v.w - h.w);
            *(float4*)&Bhi[r * BLD + c4 * 4] = h;
            *(float4*)&Blo[r * BLD + c4 * 4] = o;
        }
        __syncthreads();

#pragma unroll
        for (int ks = 0; ks < GBK; ks += 8) {
            wmma::fragment<wmma::matrix_a, 16, 16, 8, wmma::precision::tf32, wmma::row_major> ah[2], al[2];
            wmma::fragment<wmma::matrix_b, 16, 16, 8, wmma::precision::tf32, wmma::row_major> bh[4], bl[4];
#pragma unroll
            for (int i = 0; i < 2; i++) {
                const int row = warp_m * 32 + i * 16;
                wmma::load_matrix_sync(ah[i], Ahi + row * ALD + ks, ALD);
                wmma::load_matrix_sync(al[i], Alo + row * ALD + ks, ALD);
            }
#pragma unroll
            for (int j = 0; j < 4; j++) {
                const int col = warp_n * 64 + j * 16;
                wmma::load_matrix_sync(bh[j], Bhi + ks * BLD + col, BLD);
                wmma::load_matrix_sync(bl[j], Blo + ks * BLD + col, BLD);
            }
#pragma unroll
            for (int i = 0; i < 2; i++)
#pragma unroll
                for (int j = 0; j < 4; j++) {
                    wmma::mma_sync(acc[i][j], ah[i], bh[j], acc[i][j]);
                    wmma::mma_sync(acc[i][j], ah[i], bl[j], acc[i][j]);
                    wmma::mma_sync(acc[i][j], al[i], bh[j], acc[i][j]);
                }
        }
        __syncthreads();
    }

    // ---- epilogue: stage via smem, add bias, coalesced store ----
#pragma unroll
    for (int i = 0; i < 2; i++)
#pragma unroll
        for (int j = 0; j < 4; j++)
            wmma::store_matrix_sync(Cst + (warp_m * 32 + i * 16) * CLD + warp_n * 64 + j * 16,
                                    acc[i][j], CLD, wmma::mem_row_major);
    __syncthreads();

#pragma unroll
    for (int l = 0; l < 16; l++) {             // 128 rows x 32 f4 = 4096 f4
        const int idx = tid + l * 256;
        const int r = idx >> 5, c4 = idx & 31;
        float4 v = *(float4*)&Cst[r * CLD + c4 * 4];
        v.x += bias[c4 * 4 + 0];
        v.y += bias[c4 * 4 + 1];
        v.z += bias[c4 * 4 + 2];
        v.w += bias[c4 * 4 + 3];
        *(float4*)(QKV + (size_t)(bm + r) * NQKV + bn + c4 * 4) = v;
    }
}

// ---------------------------------------------------------------------------
// Kernel B: pixel-pair one-pass local attention, SoA smem halos.
// Halos stored as 4 float4-planes (plane stride 486 slots of 16B): LDS.128 at
// 16B lane stride is phase-conflict-free with NO per-pixel padding.
// smem = 2 * 4 * 486 * 16 B = 62,208 B  -> 3 blocks/SM (12 warps).
// ---------------------------------------------------------------------------
#define TILE    16
#define HALO    22
#define NHALO   (HALO*HALO)     // 484
#define PPLANE  486             // padded plane stride (16B units)
#define ATTN_SMEM (2 * 4 * PPLANE * 16)    // 62208 B

__global__ __launch_bounds__(128)
void attn_kernel(const float* __restrict__ QKV,
                 const float* __restrict__ emb0,   // [64,7]
                 const float* __restrict__ emb1,   // [64,7]
                 float* __restrict__ out)
{
    extern __shared__ float sbuf[];
    ulonglong2* bK = (ulonglong2*)sbuf;            // planes 0..3
    ulonglong2* bV = bK + 4 * PPLANE;              // planes 0..3

    const int tid = threadIdx.x;
    const int px  = tid & 15;
    const int yp  = tid >> 4;          // 0..7
    const int tx0 = (blockIdx.x & 3) * TILE;
    const int ty0 = (blockIdx.x >> 2) * TILE;
    const int b   = blockIdx.y;
    const int h   = blockIdx.z;

    // ---- load K and V halos into SoA planes (zero-filled OOB) ----
    {
        const int koff = FILTERS + h * HSIZE;
        const int voff = 2 * FILTERS + h * HSIZE;
#pragma unroll
        for (int i = tid; i < NHALO * 4; i += 128) {
            const int hp = i >> 2, c4 = i & 3;
            const int hy = hp / HALO, hx = hp % HALO;
            const int sy = ty0 + hy - 3, sx = tx0 + hx - 3;
            float4 kv = make_float4(0.f, 0.f, 0.f, 0.f);
            float4 vv = make_float4(0.f, 0.f, 0.f, 0.f);
            if ((unsigned)sy < HH && (unsigned)sx < WW) {
                const float* base = QKV + (size_t)(((b * HH) + sy) * WW + sx) * NQKV;
                kv = *(const float4*)(base + koff + c4 * 4);
                vv = *(const float4*)(base + voff + c4 * 4);
            }
            *(float4*)&bK[c4 * PPLANE + hp] = kv;
            *(float4*)&bV[c4 * PPLANE + hp] = vv;
        }
    }

    // ---- load both q vectors as packed pairs ----
    const int y0   = ty0 + 2 * yp;
    const int pix0 = ((b * HH) + y0) * WW + (tx0 + px);
    const int pix1 = pix0 + WW;

    ull q0[8], q1[8];
    {
        const ulonglong2* qp0 = (const ulonglong2*)(QKV + (size_t)pix0 * NQKV + h * HSIZE);
        const ulonglong2* qp1 = (const ulonglong2*)(QKV + (size_t)pix1 * NQKV + h * HSIZE);
#pragma unroll
        for (int j = 0; j < 4; j++) {
            ulonglong2 t0 = qp0[j];
            ulonglong2 t1 = qp1[j];
            q0[2*j] = t0.x; q0[2*j+1] = t0.y;
            q1[2*j] = t1.x; q1[2*j+1] = t1.y;
        }
    }

    // ---- qe tables for both pixels ----
    const bool use0 = (h < 4);
    float qe0[7], qe1[7];
    {
        const float* etab = use0 ? (emb0 + h * HSIZE * K0)
                                 : (emb1 + (h * HSIZE - 64) * K1);
        float qf0[16], qf1[16];
#pragma unroll
        for (int j = 0; j < 8; j++) {
            UNPK2(qf0[2*j], qf0[2*j+1], q0[j]);
            UNPK2(qf1[2*j], qf1[2*j+1], q1[j]);
        }
#pragma unroll
        for (int r = 0; r < 7; r++) {
            float s0 = 0.f, s1 = 0.f;
#pragma unroll
            for (int d = 0; d < 16; d++) {
                const float e = etab[d * 7 + r];
                s0 += qf0[d] * e;
                s1 += qf1[d] * e;
            }
            qe0[r] = s0;
            qe1[r] = s1;
        }
    }

    __syncthreads();

    // ---- one-pass (no-max) softmax-attention over 8x7 union window ----
    float sum0 = 0.f, sum1 = 0.f;
    ull o0[8], o1[8];
#pragma unroll
    for (int j = 0; j < 8; j++) { o0[j] = 0ull; o1[j] = 0ull; }

#pragma unroll
    for (int dr = 0; dr < 8; dr++) {
#pragma unroll
        for (int dj = 0; dj < 7; dj++) {
            const int hp = (2*yp + dr) * HALO + (px + dj);
            ull kr[8], vr[8];
            {
                ulonglong2 t;
                t = bK[0*PPLANE + hp]; kr[0]=t.x; kr[1]=t.y;
                t = bK[1*PPLANE + hp]; kr[2]=t.x; kr[3]=t.y;
                t = bK[2*PPLANE + hp]; kr[4]=t.x; kr[5]=t.y;
                t = bK[3*PPLANE + hp]; kr[6]=t.x; kr[7]=t.y;
                t = bV[0*PPLANE + hp]; vr[0]=t.x; vr[1]=t.y;
                t = bV[1*PPLANE + hp]; vr[2]=t.x; vr[3]=t.y;
                t = bV[2*PPLANE + hp]; vr[4]=t.x; vr[5]=t.y;
                t = bV[3*PPLANE + hp]; vr[6]=t.x; vr[7]=t.y;
            }

            if (dr < 7) {           // pixel0: di = dr
                ull m0, m1;
                MUL2(m0, q0[0], kr[0]);
                MUL2(m1, q0[1], kr[1]);
                FMA2(m0, q0[2], kr[2]);
                FMA2(m1, q0[3], kr[3]);
                FMA2(m0, q0[4], kr[4]);
                FMA2(m1, q0[5], kr[5]);
                FMA2(m0, q0[6], kr[6]);
                FMA2(m1, q0[7], kr[7]);
                ADD2(m0, m0, m1);
                float lo, hi;
                UNPK2(lo, hi, m0);
                const float s = lo + hi + (use0 ? qe0[dr] : qe0[dj]);
                const float e = __expf(s);
                sum0 += e;
                ull ep; PACK2(ep, e, e);
#pragma unroll
                for (int j = 0; j < 8; j++) FMA2(o0[j], ep, vr[j]);
            }
            if (dr > 0) {           // pixel1: di = dr-1
                ull m0, m1;
                MUL2(m0, q1[0], kr[0]);
                MUL2(m1, q1[1], kr[1]);
                FMA2(m0, q1[2], kr[2]);
                FMA2(m1, q1[3], kr[3]);
                FMA2(m0, q1[4], kr[4]);
                FMA2(m1, q1[5], kr[5]);
                FMA2(m0, q1[6], kr[6]);
                FMA2(m1, q1[7], kr[7]);
                ADD2(m0, m0, m1);
                float lo, hi;
                UNPK2(lo, hi, m0);
                const float s = lo + hi + (use0 ? qe1[dr-1] : qe1[dj]);
                const float e = __expf(s);
                sum1 += e;
                ull ep; PACK2(ep, e, e);
#pragma unroll
                for (int j = 0; j < 8; j++) FMA2(o1[j], ep, vr[j]);
            }
        }
    }

    // ---- normalize + store both pixels ----
    const float inv0 = 1.f / sum0;
    const float inv1 = 1.f / sum1;
    float* op0 = out + (size_t)pix0 * FILTERS + h * HSIZE;
    float* op1 = out + (size_t)pix1 * FILTERS + h * HSIZE;
#pragma unroll
    for (int j = 0; j < 4; j++) {
        float a0, a1, b0, b1;
        UNPK2(a0, a1, o0[2*j]);
        UNPK2(b0, b1, o0[2*j+1]);
        float4 r0 = make_float4(a0*inv0, a1*inv0, b0*inv0, b1*inv0);
        *(float4*)(op0 + j*4) = r0;
        UNPK2(a0, a1, o1[2*j]);
        UNPK2(b0, b1, o1[2*j+1]);
        float4 r1 = make_float4(a0*inv1, a1*inv1, b0*inv1, b1*inv1);
        *(float4*)(op1 + j*4) = r1;
    }
}

// ---------------------------------------------------------------------------
extern "C" void kernel_launch(void* const* d_in, const int* in_sizes, int n_in,
                              void* d_out, int out_size)
{
    const float* x    = (const float*)d_in[0];
    const float* Wq   = (const float*)d_in[1];
    const float* bq   = (const float*)d_in[2];
    const float* Wk   = (const float*)d_in[3];
    const float* bk   = (const float*)d_in[4];
    const float* Wv   = (const float*)d_in[5];
    const float* bv   = (const float*)d_in[6];
    const float* emb0 = (const float*)d_in[7];
    const float* emb1 = (const float*)d_in[8];
    float* out = (float*)d_out;

    float* qkv = nullptr;
    cudaGetSymbolAddress((void**)&qkv, g_QKV);

    cudaFuncSetAttribute(qkv_gemm_kernel,
                         cudaFuncAttributeMaxDynamicSharedMemorySize, GEMM_SMEM);
    cudaFuncSetAttribute(attn_kernel,
                         cudaFuncAttributeMaxDynamicSharedMemorySize, ATTN_SMEM);

    dim3 gg(NPIX / GBM, NQKV / GBN);   // (128, 3)
    qkv_gemm_kernel<<<gg, 256, GEMM_SMEM>>>(x, Wq, bq, Wk, bk, Wv, bv, qkv);

    dim3 ga(16, BATCH, HEADS);         // 512 blocks
    attn_kernel<<<ga, 128, ATTN_SMEM>>>(qkv, emb0, emb1, out);
}

// round 7
// speedup vs baseline: 1.3445x; 1.3445x over previous
#include <cuda_runtime.h>
#include <math.h>

// Problem constants
#define BATCH   4
#define HH      64
#define WW      64
#define CIN     128
#define FILTERS 128
#define HEADS   8
#define HSIZE   16
#define K0      7
#define K1      7
#define KD      49
#define NPIX    (BATCH*HH*WW)      // 16384
#define NQKV    384                 // q|k|v concat

typedef unsigned long long ull;

// packed f32x2 helpers (sm_100+)
#define FMA2(d, a, b)   asm("fma.rn.f32x2 %0, %1, %2, %0;" : "+l"(d) : "l"(a), "l"(b))
#define MUL2(d, a, b)   asm("mul.rn.f32x2 %0, %1, %2;"     : "=l"(d) : "l"(a), "l"(b))
#define ADD2(d, a, b)   asm("add.rn.f32x2 %0, %1, %2;"     : "=l"(d) : "l"(a), "l"(b))
#define PACK2(d, x, y)  asm("mov.b64 %0, {%1, %2};" : "=l"(d) : "f"(x), "f"(y))
#define UNPK2(lo, hi, s) asm("mov.b64 {%0, %1}, %2;" : "=f"(lo), "=f"(hi) : "l"(s))

__device__ float g_QKV[NPIX * NQKV];

// ---------------------------------------------------------------------------
// Kernel A: exact-fp32 QKV projection with pair-packed FFMA2.
// C = X(16384x128) @ [Wq|Wk|Wv](128x384) + b
// BM=128 x BN=128 x BK=32, 256 threads (16tx x 16ty), 8M x 8N per thread.
// Accumulator acc[p][n] = (C[m0][n], C[m1][n]) pairs -> A read as LDS.64
// (m0,m1) pair (warp-broadcast), B dup pairs via PACK2.
// ---------------------------------------------------------------------------
#define GBK 32
#define XSTR 130   // even (keeps LDS.64 aligned), 2-way conflict on store only
#define WSTR 128
#define GEMM_SMEM ((2 * GBK * XSTR + 2 * GBK * WSTR) * 4)   // 66048 B

__global__ __launch_bounds__(256)
void qkv_gemm_kernel(const float* __restrict__ X,
                     const float* __restrict__ Wq, const float* __restrict__ bq,
                     const float* __restrict__ Wk, const float* __restrict__ bk,
                     const float* __restrict__ Wv, const float* __restrict__ bv,
                     float* __restrict__ QKV)
{
    extern __shared__ float gsm[];
    float* Xs = gsm;                            // [2][GBK][XSTR]
    float* Ws = gsm + 2 * GBK * XSTR;           // [2][GBK][WSTR]

    const int bm = blockIdx.x * 128;
    const int bn = blockIdx.y * 128;            // 0 / 128 / 256

    const float* W;  const float* bias;
    if (bn == 0)        { W = Wq; bias = bq; }
    else if (bn == 128) { W = Wk; bias = bk; }
    else                { W = Wv; bias = bv; }

    const int tid = threadIdx.x;
    const int tx = tid & 15;       // n-group
    const int ty = tid >> 4;       // m-group

    ull acc[4][8];                 // [m-pair][n]
#pragma unroll
    for (int p = 0; p < 4; p++)
#pragma unroll
        for (int n = 0; n < 8; n++) acc[p][n] = 0ull;

    // ---- first tiles into buffer 0 ----
#pragma unroll
    for (int l = 0; l < 4; l++) {               // X tile: 128m x 8 f4
        const int idx = tid + l * 256;
        const int r = idx >> 3, c4 = idx & 7;
        float4 v = *(const float4*)(X + (size_t)(bm + r) * CIN + c4 * 4);
        Xs[(c4*4+0) * XSTR + r] = v.x;
        Xs[(c4*4+1) * XSTR + r] = v.y;
        Xs[(c4*4+2) * XSTR + r] = v.z;
        Xs[(c4*4+3) * XSTR + r] = v.w;
    }
#pragma unroll
    for (int l = 0; l < 4; l++) {               // W tile: 32k x 32 f4
        const int idx = tid + l * 256;
        const int r = idx >> 5, c4 = idx & 31;
        *(float4*)&Ws[r * WSTR + c4 * 4] =
            *(const float4*)(W + (size_t)r * FILTERS + bn - (bn) + c4 * 4 + 0);
    }
    // NOTE: W points at the full 128-col matrix; columns are c4*4 (0..127).
    __syncthreads();

    int cur = 0;
#pragma unroll
    for (int kt = 0; kt < CIN / GBK; kt++) {
        const int k_next = (kt + 1) * GBK;
        float4 pa[4], pw[4];
        if (k_next < CIN) {
#pragma unroll
            for (int l = 0; l < 4; l++) {
                const int idx = tid + l * 256;
                const int r = idx >> 3, c4 = idx & 7;
                pa[l] = *(const float4*)(X + (size_t)(bm + r) * CIN + k_next + c4 * 4);
            }
#pragma unroll
            for (int l = 0; l < 4; l++) {
                const int idx = tid + l * 256;
                const int r = idx >> 5, c4 = idx & 31;
                pw[l] = *(const float4*)(W + (size_t)(k_next + r) * FILTERS + c4 * 4);
            }
        }

        const float* xb = Xs + cur * GBK * XSTR;
        const float* wb = Ws + cur * GBK * WSTR;
#pragma unroll
        for (int kk = 0; kk < GBK; kk++) {
            // A: 4 m-pairs, broadcast LDS.64
            ull a[4];
#pragma unroll
            for (int p = 0; p < 4; p++)
                a[p] = *(const ull*)(xb + kk * XSTR + ty * 8 + p * 2);
            // B: 8 n values -> dup pairs
            float4 b0 = *(const float4*)(wb + kk * WSTR + tx * 8);
            float4 b1 = *(const float4*)(wb + kk * WSTR + tx * 8 + 4);
            ull bb[8];
            PACK2(bb[0], b0.x, b0.x);
            PACK2(bb[1], b0.y, b0.y);
            PACK2(bb[2], b0.z, b0.z);
            PACK2(bb[3], b0.w, b0.w);
            PACK2(bb[4], b1.x, b1.x);
            PACK2(bb[5], b1.y, b1.y);
            PACK2(bb[6], b1.z, b1.z);
            PACK2(bb[7], b1.w, b1.w);
#pragma unroll
            for (int p = 0; p < 4; p++)
#pragma unroll
                for (int n = 0; n < 8; n++)
                    FMA2(acc[p][n], a[p], bb[n]);
        }

        if (k_next < CIN) {
            const int nxt = cur ^ 1;
            float* xn = Xs + nxt * GBK * XSTR;
            float* wn = Ws + nxt * GBK * WSTR;
            __syncthreads();
#pragma unroll
            for (int l = 0; l < 4; l++) {
                const int idx = tid + l * 256;
                const int r = idx >> 3, c4 = idx & 7;
                xn[(c4*4+0) * XSTR + r] = pa[l].x;
                xn[(c4*4+1) * XSTR + r] = pa[l].y;
                xn[(c4*4+2) * XSTR + r] = pa[l].z;
                xn[(c4*4+3) * XSTR + r] = pa[l].w;
            }
#pragma unroll
            for (int l = 0; l < 4; l++) {
                const int idx = tid + l * 256;
                const int r = idx >> 5, c4 = idx & 31;
                *(float4*)&wn[r * WSTR + c4 * 4] = pw[l];
            }
            __syncthreads();
            cur = nxt;
        }
    }

    // ---- epilogue: unpack pairs, add bias, store ----
    float4 bia0, bia1;
    bia0.x = bias[tx*8 + 0]; bia0.y = bias[tx*8 + 1];
    bia0.z = bias[tx*8 + 2]; bia0.w = bias[tx*8 + 3];
    bia1.x = bias[tx*8 + 4]; bia1.y = bias[tx*8 + 5];
    bia1.z = bias[tx*8 + 6]; bia1.w = bias[tx*8 + 7];
#pragma unroll
    for (int p = 0; p < 4; p++) {
        float r0[8], r1[8];
#pragma unroll
        for (int n = 0; n < 8; n++) UNPK2(r0[n], r1[n], acc[p][n]);
        const int m0 = bm + ty * 8 + p * 2;
        float* d0 = QKV + (size_t)m0 * NQKV + bn + tx * 8;
        float* d1 = d0 + NQKV;
        *(float4*)(d0)     = make_float4(r0[0]+bia0.x, r0[1]+bia0.y, r0[2]+bia0.z, r0[3]+bia0.w);
        *(float4*)(d0 + 4) = make_float4(r0[4]+bia1.x, r0[5]+bia1.y, r0[6]+bia1.z, r0[7]+bia1.w);
        *(float4*)(d1)     = make_float4(r1[0]+bia0.x, r1[1]+bia0.y, r1[2]+bia0.z, r1[3]+bia0.w);
        *(float4*)(d1 + 4) = make_float4(r1[4]+bia1.x, r1[5]+bia1.y, r1[6]+bia1.z, r1[7]+bia1.w);
    }
}

// ---------------------------------------------------------------------------
// Kernel B: pixel-pair one-pass local attention (R5 version — best measured).
// ---------------------------------------------------------------------------
#define TILE    16
#define HALO    22
#define NHALO   (HALO*HALO)     // 484
#define PSTR    20
#define ATTN_SMEM (2 * NHALO * PSTR * 4)   // 77440 B

__global__ __launch_bounds__(128)
void attn_kernel(const float* __restrict__ QKV,
                 const float* __restrict__ emb0,   // [64,7]
                 const float* __restrict__ emb1,   // [64,7]
                 float* __restrict__ out)
{
    extern __shared__ float sbuf[];
    float* bufK = sbuf;
    float* bufV = sbuf + NHALO * PSTR;

    const int tid = threadIdx.x;
    const int px  = tid & 15;
    const int yp  = tid >> 4;          // 0..7
    const int tx0 = (blockIdx.x & 3) * TILE;
    const int ty0 = (blockIdx.x >> 2) * TILE;
    const int b   = blockIdx.y;
    const int h   = blockIdx.z;

    // ---- load K and V halos (zero-filled OOB) ----
    {
        const int koff = FILTERS + h * HSIZE;
        const int voff = 2 * FILTERS + h * HSIZE;
#pragma unroll
        for (int i = tid; i < NHALO * 4; i += 128) {
            const int hp = i >> 2, c4 = i & 3;
            const int hy = hp / HALO, hx = hp % HALO;
            const int sy = ty0 + hy - 3, sx = tx0 + hx - 3;
            float4 kv = make_float4(0.f, 0.f, 0.f, 0.f);
            float4 vv = make_float4(0.f, 0.f, 0.f, 0.f);
            if ((unsigned)sy < HH && (unsigned)sx < WW) {
                const float* base = QKV + (size_t)(((b * HH) + sy) * WW + sx) * NQKV;
                kv = *(const float4*)(base + koff + c4 * 4);
                vv = *(const float4*)(base + voff + c4 * 4);
            }
            *(float4*)&bufK[hp * PSTR + c4 * 4] = kv;
            *(float4*)&bufV[hp * PSTR + c4 * 4] = vv;
        }
    }

    // ---- load both q vectors as packed pairs ----
    const int y0   = ty0 + 2 * yp;
    const int pix0 = ((b * HH) + y0) * WW + (tx0 + px);
    const int pix1 = pix0 + WW;

    ull q0[8], q1[8];
    {
        const ulonglong2* qp0 = (const ulonglong2*)(QKV + (size_t)pix0 * NQKV + h * HSIZE);
        const ulonglong2* qp1 = (const ulonglong2*)(QKV + (size_t)pix1 * NQKV + h * HSIZE);
#pragma unroll
        for (int j = 0; j < 4; j++) {
            ulonglong2 t0 = qp0[j];
            ulonglong2 t1 = qp1[j];
            q0[2*j] = t0.x; q0[2*j+1] = t0.y;
            q1[2*j] = t1.x; q1[2*j+1] = t1.y;
        }
    }

    // ---- qe tables for both pixels ----
    const bool use0 = (h < 4);
    float qe0[7], qe1[7];
    {
        const float* etab = use0 ? (emb0 + h * HSIZE * K0)
                                 : (emb1 + (h * HSIZE - 64) * K1);
        float qf0[16], qf1[16];
#pragma unroll
        for (int j = 0; j < 8; j++) {
            UNPK2(qf0[2*j], qf0[2*j+1], q0[j]);
            UNPK2(qf1[2*j], qf1[2*j+1], q1[j]);
        }
#pragma unroll
        for (int r = 0; r < 7; r++) {
            float s0 = 0.f, s1 = 0.f;
#pragma unroll
            for (int d = 0; d < 16; d++) {
                const float e = etab[d * 7 + r];
                s0 += qf0[d] * e;
                s1 += qf1[d] * e;
            }
            qe0[r] = s0;
            qe1[r] = s1;
        }
    }

    __syncthreads();

    // ---- one-pass (no-max) softmax-attention over 8x7 union window ----
    float sum0 = 0.f, sum1 = 0.f;
    ull o0[8], o1[8];
#pragma unroll
    for (int j = 0; j < 8; j++) { o0[j] = 0ull; o1[j] = 0ull; }

#pragma unroll
    for (int dr = 0; dr < 8; dr++) {
#pragma unroll
        for (int dj = 0; dj < 7; dj++) {
            const int eoff = ((2*yp + dr) * HALO + (px + dj)) * PSTR;
            const float* kp = bufK + eoff;
            const float* vp = bufV + eoff;
            ull kr[8], vr[8];
            {
                ulonglong2 t;
                t = *(const ulonglong2*)(kp +  0); kr[0]=t.x; kr[1]=t.y;
                t = *(const ulonglong2*)(kp +  4); kr[2]=t.x; kr[3]=t.y;
                t = *(const ulonglong2*)(kp +  8); kr[4]=t.x; kr[5]=t.y;
                t = *(const ulonglong2*)(kp + 12); kr[6]=t.x; kr[7]=t.y;
                t = *(const ulonglong2*)(vp +  0); vr[0]=t.x; vr[1]=t.y;
                t = *(const ulonglong2*)(vp +  4); vr[2]=t.x; vr[3]=t.y;
                t = *(const ulonglong2*)(vp +  8); vr[4]=t.x; vr[5]=t.y;
                t = *(const ulonglong2*)(vp + 12); vr[6]=t.x; vr[7]=t.y;
            }

            if (dr < 7) {           // pixel0: di = dr
                ull m0, m1;
                MUL2(m0, q0[0], kr[0]);
                MUL2(m1, q0[1], kr[1]);
                FMA2(m0, q0[2], kr[2]);
                FMA2(m1, q0[3], kr[3]);
                FMA2(m0, q0[4], kr[4]);
                FMA2(m1, q0[5], kr[5]);
                FMA2(m0, q0[6], kr[6]);
                FMA2(m1, q0[7], kr[7]);
                ADD2(m0, m0, m1);
                float lo, hi;
                UNPK2(lo, hi, m0);
                const float s = lo + hi + (use0 ? qe0[dr] : qe0[dj]);
                const float e = __expf(s);
                sum0 += e;
                ull ep; PACK2(ep, e, e);
#pragma unroll
                for (int j = 0; j < 8; j++) FMA2(o0[j], ep, vr[j]);
            }
            if (dr > 0) {           // pixel1: di = dr-1
                ull m0, m1;
                MUL2(m0, q1[0], kr[0]);
                MUL2(m1, q1[1], kr[1]);
                FMA2(m0, q1[2], kr[2]);
                FMA2(m1, q1[3], kr[3]);
                FMA2(m0, q1[4], kr[4]);
                FMA2(m1, q1[5], kr[5]);
                FMA2(m0, q1[6], kr[6]);
                FMA2(m1, q1[7], kr[7]);
                ADD2(m0, m0, m1);
                float lo, hi;
                UNPK2(lo, hi, m0);
                const float s = lo + hi + (use0 ? qe1[dr-1] : qe1[dj]);
                const float e = __expf(s);
                sum1 += e;
                ull ep; PACK2(ep, e, e);
#pragma unroll
                for (int j = 0; j < 8; j++) FMA2(o1[j], ep, vr[j]);
            }
        }
    }

    // ---- normalize + store both pixels ----
    const float inv0 = 1.f / sum0;
    const float inv1 = 1.f / sum1;
    float* op0 = out + (size_t)pix0 * FILTERS + h * HSIZE;
    float* op1 = out + (size_t)pix1 * FILTERS + h * HSIZE;
#pragma unroll
    for (int j = 0; j < 4; j++) {
        float a0, a1, b0, b1;
        UNPK2(a0, a1, o0[2*j]);
        UNPK2(b0, b1, o0[2*j+1]);
        float4 r0 = make_float4(a0*inv0, a1*inv0, b0*inv0, b1*inv0);
        *(float4*)(op0 + j*4) = r0;
        UNPK2(a0, a1, o1[2*j]);
        UNPK2(b0, b1, o1[2*j+1]);
        float4 r1 = make_float4(a0*inv1, a1*inv1, b0*inv1, b1*inv1);
        *(float4*)(op1 + j*4) = r1;
    }
}

// ---------------------------------------------------------------------------
extern "C" void kernel_launch(void* const* d_in, const int* in_sizes, int n_in,
                              void* d_out, int out_size)
{
    const float* x    = (const float*)d_in[0];
    const float* Wq   = (const float*)d_in[1];
    const float* bq   = (const float*)d_in[2];
    const float* Wk   = (const float*)d_in[3];
    const float* bk   = (const float*)d_in[4];
    const float* Wv   = (const float*)d_in[5];
    const float* bv   = (const float*)d_in[6];
    const float* emb0 = (const float*)d_in[7];
    const float* emb1 = (const float*)d_in[8];
    float* out = (float*)d_out;

    float* qkv = nullptr;
    cudaGetSymbolAddress((void**)&qkv, g_QKV);

    cudaFuncSetAttribute(qkv_gemm_kernel,
                         cudaFuncAttributeMaxDynamicSharedMemorySize, GEMM_SMEM);
    cudaFuncSetAttribute(attn_kernel,
                         cudaFuncAttributeMaxDynamicSharedMemorySize, ATTN_SMEM);

    dim3 gg(NPIX / 128, NQKV / 128);   // (128, 3)
    qkv_gemm_kernel<<<gg, 256, GEMM_SMEM>>>(x, Wq, bq, Wk, bk, Wv, bv, qkv);

    dim3 ga(16, BATCH, HEADS);         // 512 blocks
    attn_kernel<<<ga, 128, ATTN_SMEM>>>(qkv, emb0, emb1, out);
}

// round 9
// speedup vs baseline: 1.6620x; 1.2362x over previous
#include <cuda_runtime.h>
#include <cuda_bf16.h>
#include <mma.h>
#include <math.h>

using namespace nvcuda;

// Problem constants
#define BATCH   4
#define HH      64
#define WW      64
#define CIN     128
#define FILTERS 128
#define HEADS   8
#define HSIZE   16
#define K0      7
#define K1      7
#define KD      49
#define NPIX    (BATCH*HH*WW)      // 16384
#define NQKV    384                 // q|k|v concat

typedef unsigned long long ull;
typedef unsigned int u32;

// packed f32x2 helpers (sm_100+)
#define FMA2(d, a, b)   asm("fma.rn.f32x2 %0, %1, %2, %0;" : "+l"(d) : "l"(a), "l"(b))
#define MUL2(d, a, b)   asm("mul.rn.f32x2 %0, %1, %2;"     : "=l"(d) : "l"(a), "l"(b))
#define ADD2(d, a, b)   asm("add.rn.f32x2 %0, %1, %2;"     : "=l"(d) : "l"(a), "l"(b))
#define PACK2(d, x, y)  asm("mov.b64 %0, {%1, %2};" : "=l"(d) : "f"(x), "f"(y))
#define UNPK2(lo, hi, s) asm("mov.b64 {%0, %1}, %2;" : "=f"(lo), "=f"(hi) : "l"(s))

__device__ float g_QKV[NPIX * NQKV];

// ---------------------------------------------------------------------------
// Kernel A: QKV projection, bf16x3 Dekker-split WMMA (m16n16k16).
// C = X(16384x128) @ [Wq|Wk|Wv](128x384) + b      (per-kind N=128 blocks)
// D = Xhi*Whi + Xlo*Whi + Xhi*Wlo, fp32 accum -> ~1e-5 rel err.
// Block: BM=128 x BN=128 x BK=32, 256 thr (8 warps 4x2, warp tile 32x64).
// bf16 tiles padded to odd-16B row strides (ALD=40, BLD=136): conflict-free
// LDSM fragment loads.
// ---------------------------------------------------------------------------
#define GBK 32
#define ALD 40       // bf16 elems per A row (80 B)
#define BLD 136      // bf16 elems per B row (272 B)
#define CLD 132      // fp32 staging stride
#define A_BYTES (128 * ALD * 2)      // 10240
#define B_BYTES (GBK * BLD * 2)      // 8704
#define GEMM_SMEM (128 * CLD * 4)    // 67584 (union; > 2*A + 2*B = 37888)

__device__ __forceinline__ void split4(float4 v, ull& hi, ull& lo) {
    __nv_bfloat16 h0 = __float2bfloat16_rn(v.x);
    __nv_bfloat16 h1 = __float2bfloat16_rn(v.y);
    __nv_bfloat16 h2 = __float2bfloat16_rn(v.z);
    __nv_bfloat16 h3 = __float2bfloat16_rn(v.w);
    __nv_bfloat16 l0 = __float2bfloat16_rn(v.x - __bfloat162float(h0));
    __nv_bfloat16 l1 = __float2bfloat16_rn(v.y - __bfloat162float(h1));
    __nv_bfloat16 l2 = __float2bfloat16_rn(v.z - __bfloat162float(h2));
    __nv_bfloat16 l3 = __float2bfloat16_rn(v.w - __bfloat162float(h3));
    unsigned short s0 = *(unsigned short*)&h0, s1 = *(unsigned short*)&h1;
    unsigned short s2 = *(unsigned short*)&h2, s3 = *(unsigned short*)&h3;
    hi = (ull)s0 | ((ull)s1 << 16) | ((ull)s2 << 32) | ((ull)s3 << 48);
    s0 = *(unsigned short*)&l0; s1 = *(unsigned short*)&l1;
    s2 = *(unsigned short*)&l2; s3 = *(unsigned short*)&l3;
    lo = (ull)s0 | ((ull)s1 << 16) | ((ull)s2 << 32) | ((ull)s3 << 48);
}

__global__ __launch_bounds__(256)
void qkv_gemm_kernel(const float* __restrict__ X,
                     const float* __restrict__ Wq, const float* __restrict__ bq,
                     const float* __restrict__ Wk, const float* __restrict__ bk,
                     const float* __restrict__ Wv, const float* __restrict__ bv,
                     float* __restrict__ QKV)
{
    extern __shared__ __align__(16) char smem[];
    __nv_bfloat16* Ahi = (__nv_bfloat16*)smem;
    __nv_bfloat16* Alo = Ahi + 128 * ALD;
    __nv_bfloat16* Bhi = (__nv_bfloat16*)(smem + 2 * A_BYTES);
    __nv_bfloat16* Blo = Bhi + GBK * BLD;
    float* Cst = (float*)smem;

    const int bm = blockIdx.x * 128;
    const int bn = blockIdx.y * 128;     // 0 / 128 / 256 -> q / k / v

    const float* W;  const float* bias;
    if (bn == 0)        { W = Wq; bias = bq; }
    else if (bn == 128) { W = Wk; bias = bk; }
    else                { W = Wv; bias = bv; }

    const int tid = threadIdx.x;
    const int wid = tid >> 5;
    const int warp_m = wid & 3;          // 4 row-warps x 32 rows
    const int warp_n = wid >> 2;         // 2 col-warps x 64 cols

    wmma::fragment<wmma::accumulator, 16, 16, 16, float> acc[2][4];
#pragma unroll
    for (int i = 0; i < 2; i++)
#pragma unroll
        for (int j = 0; j < 4; j++) wmma::fill_fragment(acc[i][j], 0.f);

#pragma unroll
    for (int kt = 0; kt < CIN; kt += GBK) {
        // ---- load + split A tile: 128 x 32 fp32 -> bf16 hi/lo ----
#pragma unroll
        for (int l = 0; l < 4; l++) {
            const int idx = tid + l * 256;
            const int r = idx >> 3, c4 = idx & 7;
            float4 v = *(const float4*)(X + (size_t)(bm + r) * CIN + kt + c4 * 4);
            ull hi, lo;
            split4(v, hi, lo);
            *(ull*)&Ahi[r * ALD + c4 * 4] = hi;
            *(ull*)&Alo[r * ALD + c4 * 4] = lo;
        }
        // ---- load + split B tile: 32 x 128 fp32 -> bf16 hi/lo (B[k][n]) ----
#pragma unroll
        for (int l = 0; l < 4; l++) {
            const int idx = tid + l * 256;
            const int r = idx >> 5, c4 = idx & 31;
            float4 v = *(const float4*)(W + (size_t)(kt + r) * FILTERS + c4 * 4);
            ull hi, lo;
            split4(v, hi, lo);
            *(ull*)&Bhi[r * BLD + c4 * 4] = hi;
            *(ull*)&Blo[r * BLD + c4 * 4] = lo;
        }
        __syncthreads();

#pragma unroll
        for (int ks = 0; ks < GBK; ks += 16) {
            wmma::fragment<wmma::matrix_a, 16, 16, 16, __nv_bfloat16, wmma::row_major> ah[2], al[2];
            wmma::fragment<wmma::matrix_b, 16, 16, 16, __nv_bfloat16, wmma::row_major> bh[4], bl[4];
#pragma unroll
            for (int i = 0; i < 2; i++) {
                const int row = warp_m * 32 + i * 16;
                wmma::load_matrix_sync(ah[i], Ahi + row * ALD + ks, ALD);
                wmma::load_matrix_sync(al[i], Alo + row * ALD + ks, ALD);
            }
#pragma unroll
            for (int j = 0; j < 4; j++) {
                const int col = warp_n * 64 + j * 16;
                wmma::load_matrix_sync(bh[j], Bhi + ks * BLD + col, BLD);
                wmma::load_matrix_sync(bl[j], Blo + ks * BLD + col, BLD);
            }
#pragma unroll
            for (int i = 0; i < 2; i++)
#pragma unroll
                for (int j = 0; j < 4; j++) {
                    wmma::mma_sync(acc[i][j], ah[i], bh[j], acc[i][j]);
                    wmma::mma_sync(acc[i][j], al[i], bh[j], acc[i][j]);
                    wmma::mma_sync(acc[i][j], ah[i], bl[j], acc[i][j]);
                }
        }
        __syncthreads();
    }

    // ---- epilogue: stage via smem, add bias, coalesced fp32 store ----
#pragma unroll
    for (int i = 0; i < 2; i++)
#pragma unroll
        for (int j = 0; j < 4; j++)
            wmma::store_matrix_sync(Cst + (warp_m * 32 + i * 16) * CLD + warp_n * 64 + j * 16,
                                    acc[i][j], CLD, wmma::mem_row_major);
    __syncthreads();

#pragma unroll
    for (int l = 0; l < 16; l++) {             // 128 rows x 32 f4
        const int idx = tid + l * 256;
        const int r = idx >> 5, c4 = idx & 31;
        float4 v = *(float4*)&Cst[r * CLD + c4 * 4];
        v.x += bias[c4 * 4 + 0];
        v.y += bias[c4 * 4 + 1];
        v.z += bias[c4 * 4 + 2];
        v.w += bias[c4 * 4 + 3];
        *(float4*)(QKV + (size_t)(bm + r) * NQKV + bn + c4 * 4) = v;
    }
}

// ---------------------------------------------------------------------------
// Kernel B: pixel-pair one-pass local attention (best measured config, R5).
// ---------------------------------------------------------------------------
#define TILE    16
#define HALO    22
#define NHALO   (HALO*HALO)     // 484
#define PSTR    20
#define ATTN_SMEM (2 * NHALO * PSTR * 4)   // 77440 B

__global__ __launch_bounds__(128)
void attn_kernel(const float* __restrict__ QKV,
                 const float* __restrict__ emb0,   // [64,7]
                 const float* __restrict__ emb1,   // [64,7]
                 float* __restrict__ out)
{
    extern __shared__ float sbuf[];
    float* bufK = sbuf;
    float* bufV = sbuf + NHALO * PSTR;

    const int tid = threadIdx.x;
    const int px  = tid & 15;
    const int yp  = tid >> 4;          // 0..7
    const int tx0 = (blockIdx.x & 3) * TILE;
    const int ty0 = (blockIdx.x >> 2) * TILE;
    const int b   = blockIdx.y;
    const int h   = blockIdx.z;

    {
        const int koff = FILTERS + h * HSIZE;
        const int voff = 2 * FILTERS + h * HSIZE;
#pragma unroll
        for (int i = tid; i < NHALO * 4; i += 128) {
            const int hp = i >> 2, c4 = i & 3;
            const int hy = hp / HALO, hx = hp % HALO;
            const int sy = ty0 + hy - 3, sx = tx0 + hx - 3;
            float4 kv = make_float4(0.f, 0.f, 0.f, 0.f);
            float4 vv = make_float4(0.f, 0.f, 0.f, 0.f);
            if ((unsigned)sy < HH && (unsigned)sx < WW) {
                const float* base = QKV + (size_t)(((b * HH) + sy) * WW + sx) * NQKV;
                kv = *(const float4*)(base + koff + c4 * 4);
                vv = *(const float4*)(base + voff + c4 * 4);
            }
            *(float4*)&bufK[hp * PSTR + c4 * 4] = kv;
            *(float4*)&bufV[hp * PSTR + c4 * 4] = vv;
        }
    }

    const int y0   = ty0 + 2 * yp;
    const int pix0 = ((b * HH) + y0) * WW + (tx0 + px);
    const int pix1 = pix0 + WW;

    ull q0[8], q1[8];
    {
        const ulonglong2* qp0 = (const ulonglong2*)(QKV + (size_t)pix0 * NQKV + h * HSIZE);
        const ulonglong2* qp1 = (const ulonglong2*)(QKV + (size_t)pix1 * NQKV + h * HSIZE);
#pragma unroll
        for (int j = 0; j < 4; j++) {
            ulonglong2 t0 = qp0[j];
            ulonglong2 t1 = qp1[j];
            q0[2*j] = t0.x; q0[2*j+1] = t0.y;
            q1[2*j] = t1.x; q1[2*j+1] = t1.y;
        }
    }

    const bool use0 = (h < 4);
    float qe0[7], qe1[7];
    {
        const float* etab = use0 ? (emb0 + h * HSIZE * K0)
                                 : (emb1 + (h * HSIZE - 64) * K1);
        float qf0[16], qf1[16];
#pragma unroll
        for (int j = 0; j < 8; j++) {
            UNPK2(qf0[2*j], qf0[2*j+1], q0[j]);
            UNPK2(qf1[2*j], qf1[2*j+1], q1[j]);
        }
#pragma unroll
        for (int r = 0; r < 7; r++) {
            float s0 = 0.f, s1 = 0.f;
#pragma unroll
            for (int d = 0; d < 16; d++) {
                const float e = etab[d * 7 + r];
                s0 += qf0[d] * e;
                s1 += qf1[d] * e;
            }
            qe0[r] = s0;
            qe1[r] = s1;
        }
    }

    __syncthreads();

    float sum0 = 0.f, sum1 = 0.f;
    ull o0[8], o1[8];
#pragma unroll
    for (int j = 0; j < 8; j++) { o0[j] = 0ull; o1[j] = 0ull; }

#pragma unroll
    for (int dr = 0; dr < 8; dr++) {
#pragma unroll
        for (int dj = 0; dj < 7; dj++) {
            const int eoff = ((2*yp + dr) * HALO + (px + dj)) * PSTR;
            const float* kp = bufK + eoff;
            const float* vp = bufV + eoff;
            ull kr[8], vr[8];
            {
                ulonglong2 t;
                t = *(const ulonglong2*)(kp +  0); kr[0]=t.x; kr[1]=t.y;
                t = *(const ulonglong2*)(kp +  4); kr[2]=t.x; kr[3]=t.y;
                t = *(const ulonglong2*)(kp +  8); kr[4]=t.x; kr[5]=t.y;
                t = *(const ulonglong2*)(kp + 12); kr[6]=t.x; kr[7]=t.y;
                t = *(const ulonglong2*)(vp +  0); vr[0]=t.x; vr[1]=t.y;
                t = *(const ulonglong2*)(vp +  4); vr[2]=t.x; vr[3]=t.y;
                t = *(const ulonglong2*)(vp +  8); vr[4]=t.x; vr[5]=t.y;
                t = *(const ulonglong2*)(vp + 12); vr[6]=t.x; vr[7]=t.y;
            }

            if (dr < 7) {
                ull m0, m1;
                MUL2(m0, q0[0], kr[0]);
                MUL2(m1, q0[1], kr[1]);
                FMA2(m0, q0[2], kr[2]);
                FMA2(m1, q0[3], kr[3]);
                FMA2(m0, q0[4], kr[4]);
                FMA2(m1, q0[5], kr[5]);
                FMA2(m0, q0[6], kr[6]);
                FMA2(m1, q0[7], kr[7]);
                ADD2(m0, m0, m1);
                float lo, hi;
                UNPK2(lo, hi, m0);
                const float s = lo + hi + (use0 ? qe0[dr] : qe0[dj]);
                const float e = __expf(s);
                sum0 += e;
                ull ep; PACK2(ep, e, e);
#pragma unroll
                for (int j = 0; j < 8; j++) FMA2(o0[j], ep, vr[j]);
            }
            if (dr > 0) {
                ull m0, m1;
                MUL2(m0, q1[0], kr[0]);
                MUL2(m1, q1[1], kr[1]);
                FMA2(m0, q1[2], kr[2]);
                FMA2(m1, q1[3], kr[3]);
                FMA2(m0, q1[4], kr[4]);
                FMA2(m1, q1[5], kr[5]);
                FMA2(m0, q1[6], kr[6]);
                FMA2(m1, q1[7], kr[7]);
                ADD2(m0, m0, m1);
                float lo, hi;
                UNPK2(lo, hi, m0);
                const float s = lo + hi + (use0 ? qe1[dr-1] : qe1[dj]);
                const float e = __expf(s);
                sum1 += e;
                ull ep; PACK2(ep, e, e);
#pragma unroll
                for (int j = 0; j < 8; j++) FMA2(o1[j], ep, vr[j]);
            }
        }
    }

    const float inv0 = 1.f / sum0;
    const float inv1 = 1.f / sum1;
    float* op0 = out + (size_t)pix0 * FILTERS + h * HSIZE;
    float* op1 = out + (size_t)pix1 * FILTERS + h * HSIZE;
#pragma unroll
    for (int j = 0; j < 4; j++) {
        float a0, a1, b0, b1;
        UNPK2(a0, a1, o0[2*j]);
        UNPK2(b0, b1, o0[2*j+1]);
        float4 r0 = make_float4(a0*inv0, a1*inv0, b0*inv0, b1*inv0);
        *(float4*)(op0 + j*4) = r0;
        UNPK2(a0, a1, o1[2*j]);
        UNPK2(b0, b1, o1[2*j+1]);
        float4 r1 = make_float4(a0*inv1, a1*inv1, b0*inv1, b1*inv1);
        *(float4*)(op1 + j*4) = r1;
    }
}

// ---------------------------------------------------------------------------
extern "C" void kernel_launch(void* const* d_in, const int* in_sizes, int n_in,
                              void* d_out, int out_size)
{
    const float* x    = (const float*)d_in[0];
    const float* Wq   = (const float*)d_in[1];
    const float* bq   = (const float*)d_in[2];
    const float* Wk   = (const float*)d_in[3];
    const float* bk   = (const float*)d_in[4];
    const float* Wv   = (const float*)d_in[5];
    const float* bv   = (const float*)d_in[6];
    const float* emb0 = (const float*)d_in[7];
    const float* emb1 = (const float*)d_in[8];
    float* out = (float*)d_out;

    float* qkv = nullptr;
    cudaGetSymbolAddress((void**)&qkv, g_QKV);

    cudaFuncSetAttribute(qkv_gemm_kernel,
                         cudaFuncAttributeMaxDynamicSharedMemorySize, GEMM_SMEM);
    cudaFuncSetAttribute(attn_kernel,
                         cudaFuncAttributeMaxDynamicSharedMemorySize, ATTN_SMEM);

    dim3 gg(NPIX / 128, 3);
    qkv_gemm_kernel<<<gg, 256, GEMM_SMEM>>>(x, Wq, bq, Wk, bk, Wv, bv, qkv);

    dim3 ga(16, BATCH, HEADS);         // 512 blocks
    attn_kernel<<<ga, 128, ATTN_SMEM>>>(qkv, emb0, emb1, out);
}

// round 10
// speedup vs baseline: 1.7680x; 1.0638x over previous
#include <cuda_runtime.h>
#include <cuda_bf16.h>
#include <mma.h>
#include <math.h>

using namespace nvcuda;

// Problem constants
#define BATCH   4
#define HH      64
#define WW      64
#define CIN     128
#define FILTERS 128
#define HEADS   8
#define HSIZE   16
#define K0      7
#define K1      7
#define KD      49
#define NPIX    (BATCH*HH*WW)      // 16384
#define NQKV    384                 // q|k|v concat

typedef unsigned long long ull;
typedef unsigned int u32;

// packed f32x2 helpers (sm_100+)
#define FMA2(d, a, b)   asm("fma.rn.f32x2 %0, %1, %2, %0;" : "+l"(d) : "l"(a), "l"(b))
#define MUL2(d, a, b)   asm("mul.rn.f32x2 %0, %1, %2;"     : "=l"(d) : "l"(a), "l"(b))
#define ADD2(d, a, b)   asm("add.rn.f32x2 %0, %1, %2;"     : "=l"(d) : "l"(a), "l"(b))
#define PACK2(d, x, y)  asm("mov.b64 %0, {%1, %2};" : "=l"(d) : "f"(x), "f"(y))
#define UNPK2(lo, hi, s) asm("mov.b64 {%0, %1}, %2;" : "=f"(lo), "=f"(hi) : "l"(s))

__device__ float g_QKV[NPIX * NQKV];

// pre-split bf16 hi/lo storage (4 bf16 per ull)
#define XCHUNKS (NPIX * CIN / 4)     // 524288
#define WCHUNKS (3 * CIN * FILTERS / 4)   // 12288
__device__ ull g_Xhi[XCHUNKS];
__device__ ull g_Xlo[XCHUNKS];
__device__ ull g_Whi[WCHUNKS];
__device__ ull g_Wlo[WCHUNKS];

__device__ __forceinline__ void split4(float4 v, ull& hi, ull& lo) {
    __nv_bfloat16 h0 = __float2bfloat16_rn(v.x);
    __nv_bfloat16 h1 = __float2bfloat16_rn(v.y);
    __nv_bfloat16 h2 = __float2bfloat16_rn(v.z);
    __nv_bfloat16 h3 = __float2bfloat16_rn(v.w);
    __nv_bfloat16 l0 = __float2bfloat16_rn(v.x - __bfloat162float(h0));
    __nv_bfloat16 l1 = __float2bfloat16_rn(v.y - __bfloat162float(h1));
    __nv_bfloat16 l2 = __float2bfloat16_rn(v.z - __bfloat162float(h2));
    __nv_bfloat16 l3 = __float2bfloat16_rn(v.w - __bfloat162float(h3));
    unsigned short s0 = *(unsigned short*)&h0, s1 = *(unsigned short*)&h1;
    unsigned short s2 = *(unsigned short*)&h2, s3 = *(unsigned short*)&h3;
    hi = (ull)s0 | ((ull)s1 << 16) | ((ull)s2 << 32) | ((ull)s3 << 48);
    s0 = *(unsigned short*)&l0; s1 = *(unsigned short*)&l1;
    s2 = *(unsigned short*)&l2; s3 = *(unsigned short*)&l3;
    lo = (ull)s0 | ((ull)s1 << 16) | ((ull)s2 << 32) | ((ull)s3 << 48);
}

// ---------------------------------------------------------------------------
// Kernel 0: pre-split X, Wq, Wk, Wv into bf16 hi/lo (Dekker).
// ---------------------------------------------------------------------------
__global__ __launch_bounds__(256)
void presplit_kernel(const float* __restrict__ X,
                     const float* __restrict__ Wq,
                     const float* __restrict__ Wk,
                     const float* __restrict__ Wv)
{
    const int idx = blockIdx.x * 256 + threadIdx.x;
    if (idx < XCHUNKS) {
        float4 v = ((const float4*)X)[idx];
        ull hi, lo;
        split4(v, hi, lo);
        g_Xhi[idx] = hi;
        g_Xlo[idx] = lo;
    } else {
        const int widx = idx - XCHUNKS;
        if (widx < WCHUNKS) {
            const int kind = widx / (WCHUNKS / 3);
            const int off  = widx % (WCHUNKS / 3);
            const float* W = (kind == 0) ? Wq : (kind == 1) ? Wk : Wv;
            float4 v = ((const float4*)W)[off];
            ull hi, lo;
            split4(v, hi, lo);
            g_Whi[widx] = hi;
            g_Wlo[widx] = lo;
        }
    }
}

// ---------------------------------------------------------------------------
// Kernel A: pure-bf16 x3 WMMA GEMM, K=128 fully smem-resident.
// D = Xhi*Whi + Xlo*Whi + Xhi*Wlo  (fp32 accum, ~1e-5 rel err)
// Block: BM=128 x BN=128 (one kind), 256 thr (8 warps 4x2, warp 32x64).
// Tiles 128x128 bf16 with 136-elem row stride (272 B, odd-16B): LDSM clean.
// ---------------------------------------------------------------------------
#define TLD 136
#define TILE_E (128 * TLD)                 // bf16 elems per tile
#define CLD 132
#define GEMM_SMEM (4 * TILE_E * 2)         // 139264 B (Cst 67584 aliases)

__global__ __launch_bounds__(256)
void qkv_gemm_kernel(const float* __restrict__ bq,
                     const float* __restrict__ bk,
                     const float* __restrict__ bv,
                     float* __restrict__ QKV)
{
    extern __shared__ __align__(16) char smem[];
    __nv_bfloat16* Ahi = (__nv_bfloat16*)smem;
    __nv_bfloat16* Alo = Ahi + TILE_E;
    __nv_bfloat16* Bhi = Alo + TILE_E;
    __nv_bfloat16* Blo = Bhi + TILE_E;
    float* Cst = (float*)smem;

    const int bm   = blockIdx.x * 128;
    const int kind = blockIdx.y;           // 0/1/2 -> q/k/v
    const int bn   = kind * 128;
    const float* bias = (kind == 0) ? bq : (kind == 1) ? bk : bv;

    const int tid = threadIdx.x;
    const int wid = tid >> 5;
    const int warp_m = wid & 3;
    const int warp_n = wid >> 2;

    // ---- single load phase: A/B hi+lo tiles (bf16, uint4 = 8 elems) ----
#pragma unroll
    for (int l = 0; l < 8; l++) {
        const int idx = tid + l * 256;     // 0..2047
        const int r = idx >> 4, c = idx & 15;
        const int gsrc = (bm + r) * 16 + c;          // uint4 index into X arrays
        *(uint4*)&Ahi[r * TLD + c * 8] = ((const uint4*)g_Xhi)[gsrc];
        *(uint4*)&Alo[r * TLD + c * 8] = ((const uint4*)g_Xlo)[gsrc];
        const int wsrc = kind * 2048 + r * 16 + c;   // uint4 index into W arrays
        *(uint4*)&Bhi[r * TLD + c * 8] = ((const uint4*)g_Whi)[wsrc];
        *(uint4*)&Blo[r * TLD + c * 8] = ((const uint4*)g_Wlo)[wsrc];
    }
    __syncthreads();

    wmma::fragment<wmma::accumulator, 16, 16, 16, float> acc[2][4];
#pragma unroll
    for (int i = 0; i < 2; i++)
#pragma unroll
        for (int j = 0; j < 4; j++) wmma::fill_fragment(acc[i][j], 0.f);

#pragma unroll
    for (int ks = 0; ks < CIN; ks += 16) {
        wmma::fragment<wmma::matrix_a, 16, 16, 16, __nv_bfloat16, wmma::row_major> ah[2], al[2];
        wmma::fragment<wmma::matrix_b, 16, 16, 16, __nv_bfloat16, wmma::row_major> bh[4], bl[4];
#pragma unroll
        for (int i = 0; i < 2; i++) {
            const int row = warp_m * 32 + i * 16;
            wmma::load_matrix_sync(ah[i], Ahi + row * TLD + ks, TLD);
            wmma::load_matrix_sync(al[i], Alo + row * TLD + ks, TLD);
        }
#pragma unroll
        for (int j = 0; j < 4; j++) {
            const int col = warp_n * 64 + j * 16;
            wmma::load_matrix_sync(bh[j], Bhi + ks * TLD + col, TLD);
            wmma::load_matrix_sync(bl[j], Blo + ks * TLD + col, TLD);
        }
#pragma unroll
        for (int i = 0; i < 2; i++)
#pragma unroll
            for (int j = 0; j < 4; j++) {
                wmma::mma_sync(acc[i][j], ah[i], bh[j], acc[i][j]);
                wmma::mma_sync(acc[i][j], al[i], bh[j], acc[i][j]);
                wmma::mma_sync(acc[i][j], ah[i], bl[j], acc[i][j]);
            }
    }

    // ---- epilogue: stage (aliases tiles after sync), add bias, store ----
    __syncthreads();
#pragma unroll
    for (int i = 0; i < 2; i++)
#pragma unroll
        for (int j = 0; j < 4; j++)
            wmma::store_matrix_sync(Cst + (warp_m * 32 + i * 16) * CLD + warp_n * 64 + j * 16,
                                    acc[i][j], CLD, wmma::mem_row_major);
    __syncthreads();

#pragma unroll
    for (int l = 0; l < 16; l++) {
        const int idx = tid + l * 256;
        const int r = idx >> 5, c4 = idx & 31;
        float4 v = *(float4*)&Cst[r * CLD + c4 * 4];
        v.x += bias[c4 * 4 + 0];
        v.y += bias[c4 * 4 + 1];
        v.z += bias[c4 * 4 + 2];
        v.w += bias[c4 * 4 + 3];
        *(float4*)(QKV + (size_t)(bm + r) * NQKV + bn + c4 * 4) = v;
    }
}

// ---------------------------------------------------------------------------
// Kernel B: pixel-pair one-pass local attention (best measured config).
// ---------------------------------------------------------------------------
#define TILE    16
#define HALO    22
#define NHALO   (HALO*HALO)     // 484
#define PSTR    20
#define ATTN_SMEM (2 * NHALO * PSTR * 4)   // 77440 B

__global__ __launch_bounds__(128)
void attn_kernel(const float* __restrict__ QKV,
                 const float* __restrict__ emb0,   // [64,7]
                 const float* __restrict__ emb1,   // [64,7]
                 float* __restrict__ out)
{
    extern __shared__ float sbuf[];
    float* bufK = sbuf;
    float* bufV = sbuf + NHALO * PSTR;

    const int tid = threadIdx.x;
    const int px  = tid & 15;
    const int yp  = tid >> 4;          // 0..7
    const int tx0 = (blockIdx.x & 3) * TILE;
    const int ty0 = (blockIdx.x >> 2) * TILE;
    const int b   = blockIdx.y;
    const int h   = blockIdx.z;

    {
        const int koff = FILTERS + h * HSIZE;
        const int voff = 2 * FILTERS + h * HSIZE;
#pragma unroll
        for (int i = tid; i < NHALO * 4; i += 128) {
            const int hp = i >> 2, c4 = i & 3;
            const int hy = hp / HALO, hx = hp % HALO;
            const int sy = ty0 + hy - 3, sx = tx0 + hx - 3;
            float4 kv = make_float4(0.f, 0.f, 0.f, 0.f);
            float4 vv = make_float4(0.f, 0.f, 0.f, 0.f);
            if ((unsigned)sy < HH && (unsigned)sx < WW) {
                const float* base = QKV + (size_t)(((b * HH) + sy) * WW + sx) * NQKV;
                kv = *(const float4*)(base + koff + c4 * 4);
                vv = *(const float4*)(base + voff + c4 * 4);
            }
            *(float4*)&bufK[hp * PSTR + c4 * 4] = kv;
            *(float4*)&bufV[hp * PSTR + c4 * 4] = vv;
        }
    }

    const int y0   = ty0 + 2 * yp;
    const int pix0 = ((b * HH) + y0) * WW + (tx0 + px);
    const int pix1 = pix0 + WW;

    ull q0[8], q1[8];
    {
        const ulonglong2* qp0 = (const ulonglong2*)(QKV + (size_t)pix0 * NQKV + h * HSIZE);
        const ulonglong2* qp1 = (const ulonglong2*)(QKV + (size_t)pix1 * NQKV + h * HSIZE);
#pragma unroll
        for (int j = 0; j < 4; j++) {
            ulonglong2 t0 = qp0[j];
            ulonglong2 t1 = qp1[j];
            q0[2*j] = t0.x; q0[2*j+1] = t0.y;
            q1[2*j] = t1.x; q1[2*j+1] = t1.y;
        }
    }

    const bool use0 = (h < 4);
    float qe0[7], qe1[7];
    {
        const float* etab = use0 ? (emb0 + h * HSIZE * K0)
                                 : (emb1 + (h * HSIZE - 64) * K1);
        float qf0[16], qf1[16];
#pragma unroll
        for (int j = 0; j < 8; j++) {
            UNPK2(qf0[2*j], qf0[2*j+1], q0[j]);
            UNPK2(qf1[2*j], qf1[2*j+1], q1[j]);
        }
#pragma unroll
        for (int r = 0; r < 7; r++) {
            float s0 = 0.f, s1 = 0.f;
#pragma unroll
            for (int d = 0; d < 16; d++) {
                const float e = etab[d * 7 + r];
                s0 += qf0[d] * e;
                s1 += qf1[d] * e;
            }
            qe0[r] = s0;
            qe1[r] = s1;
        }
    }

    __syncthreads();

    float sum0 = 0.f, sum1 = 0.f;
    ull o0[8], o1[8];
#pragma unroll
    for (int j = 0; j < 8; j++) { o0[j] = 0ull; o1[j] = 0ull; }

#pragma unroll
    for (int dr = 0; dr < 8; dr++) {
#pragma unroll
        for (int dj = 0; dj < 7; dj++) {
            const int eoff = ((2*yp + dr) * HALO + (px + dj)) * PSTR;
            const float* kp = bufK + eoff;
            const float* vp = bufV + eoff;
            ull kr[8], vr[8];
            {
                ulonglong2 t;
                t = *(const ulonglong2*)(kp +  0); kr[0]=t.x; kr[1]=t.y;
                t = *(const ulonglong2*)(kp +  4); kr[2]=t.x; kr[3]=t.y;
                t = *(const ulonglong2*)(kp +  8); kr[4]=t.x; kr[5]=t.y;
                t = *(const ulonglong2*)(kp + 12); kr[6]=t.x; kr[7]=t.y;
                t = *(const ulonglong2*)(vp +  0); vr[0]=t.x; vr[1]=t.y;
                t = *(const ulonglong2*)(vp +  4); vr[2]=t.x; vr[3]=t.y;
                t = *(const ulonglong2*)(vp +  8); vr[4]=t.x; vr[5]=t.y;
                t = *(const ulonglong2*)(vp + 12); vr[6]=t.x; vr[7]=t.y;
            }

            if (dr < 7) {
                ull m0, m1;
                MUL2(m0, q0[0], kr[0]);
                MUL2(m1, q0[1], kr[1]);
                FMA2(m0, q0[2], kr[2]);
                FMA2(m1, q0[3], kr[3]);
                FMA2(m0, q0[4], kr[4]);
                FMA2(m1, q0[5], kr[5]);
                FMA2(m0, q0[6], kr[6]);
                FMA2(m1, q0[7], kr[7]);
                ADD2(m0, m0, m1);
                float lo, hi;
                UNPK2(lo, hi, m0);
                const float s = lo + hi + (use0 ? qe0[dr] : qe0[dj]);
                const float e = __expf(s);
                sum0 += e;
                ull ep; PACK2(ep, e, e);
#pragma unroll
                for (int j = 0; j < 8; j++) FMA2(o0[j], ep, vr[j]);
            }
            if (dr > 0) {
                ull m0, m1;
                MUL2(m0, q1[0], kr[0]);
                MUL2(m1, q1[1], kr[1]);
                FMA2(m0, q1[2], kr[2]);
                FMA2(m1, q1[3], kr[3]);
                FMA2(m0, q1[4], kr[4]);
                FMA2(m1, q1[5], kr[5]);
                FMA2(m0, q1[6], kr[6]);
                FMA2(m1, q1[7], kr[7]);
                ADD2(m0, m0, m1);
                float lo, hi;
                UNPK2(lo, hi, m0);
                const float s = lo + hi + (use0 ? qe1[dr-1] : qe1[dj]);
                const float e = __expf(s);
                sum1 += e;
                ull ep; PACK2(ep, e, e);
#pragma unroll
                for (int j = 0; j < 8; j++) FMA2(o1[j], ep, vr[j]);
            }
        }
    }

    const float inv0 = 1.f / sum0;
    const float inv1 = 1.f / sum1;
    float* op0 = out + (size_t)pix0 * FILTERS + h * HSIZE;
    float* op1 = out + (size_t)pix1 * FILTERS + h * HSIZE;
#pragma unroll
    for (int j = 0; j < 4; j++) {
        float a0, a1, b0, b1;
        UNPK2(a0, a1, o0[2*j]);
        UNPK2(b0, b1, o0[2*j+1]);
        float4 r0 = make_float4(a0*inv0, a1*inv0, b0*inv0, b1*inv0);
        *(float4*)(op0 + j*4) = r0;
        UNPK2(a0, a1, o1[2*j]);
        UNPK2(b0, b1, o1[2*j+1]);
        float4 r1 = make_float4(a0*inv1, a1*inv1, b0*inv1, b1*inv1);
        *(float4*)(op1 + j*4) = r1;
    }
}

// ---------------------------------------------------------------------------
extern "C" void kernel_launch(void* const* d_in, const int* in_sizes, int n_in,
                              void* d_out, int out_size)
{
    const float* x    = (const float*)d_in[0];
    const float* Wq   = (const float*)d_in[1];
    const float* bq   = (const float*)d_in[2];
    const float* Wk   = (const float*)d_in[3];
    const float* bk   = (const float*)d_in[4];
    const float* Wv   = (const float*)d_in[5];
    const float* bv   = (const float*)d_in[6];
    const float* emb0 = (const float*)d_in[7];
    const float* emb1 = (const float*)d_in[8];
    float* out = (float*)d_out;

    float* qkv = nullptr;
    cudaGetSymbolAddress((void**)&qkv, g_QKV);

    cudaFuncSetAttribute(qkv_gemm_kernel,
                         cudaFuncAttributeMaxDynamicSharedMemorySize, GEMM_SMEM);
    cudaFuncSetAttribute(attn_kernel,
                         cudaFuncAttributeMaxDynamicSharedMemorySize, ATTN_SMEM);

    const int total_chunks = XCHUNKS + WCHUNKS;
    presplit_kernel<<<(total_chunks + 255) / 256, 256>>>(x, Wq, Wk, Wv);

    dim3 gg(NPIX / 128, 3);
    qkv_gemm_kernel<<<gg, 256, GEMM_SMEM>>>(bq, bk, bv, qkv);

    dim3 ga(16, BATCH, HEADS);         // 512 blocks
    attn_kernel<<<ga, 128, ATTN_SMEM>>>(qkv, emb0, emb1, out);
}